// round 1
// baseline (speedup 1.0000x reference)
#include <cuda_runtime.h>

#define WARPS_PER_BLOCK 8
#define THREADS 256
#define MAX_BLOCKS 4096

__device__ __align__(16) float g_w2[64];
__device__ float g_partials[MAX_BLOCKS * 3];

__device__ __forceinline__ float wsum(float v) {
#pragma unroll
    for (int o = 16; o > 0; o >>= 1) v += __shfl_xor_sync(0xffffffffu, v, o);
    return v;
}

// -log(sigmoid(x)) = softplus(-x), numerically stable
__device__ __forceinline__ float nlsig(float x) {
    float z = -x;
    return fmaxf(z, 0.f) + log1pf(expf(-fabsf(z)));
}

// w2[d] = sum_e att_w_W[d,e] * att_v_W[64+e]
__global__ void precompute_w2(const float* __restrict__ W, const float* __restrict__ vW) {
    int d = threadIdx.x;
    float s = 0.f;
#pragma unroll 16
    for (int e = 0; e < 64; e++) s += W[d * 64 + e] * vW[64 + e];
    g_w2[d] = s;
}

__global__ void __launch_bounds__(THREADS) actr_main(
    const int* __restrict__ u_id, const int* __restrict__ anchor_i_id,
    const int* __restrict__ pos_r_id, const int* __restrict__ pos_i_id,
    const int* __restrict__ neg_r_id, const int* __restrict__ neg_i_id,
    const int* __restrict__ neg_ri_id, const int* __restrict__ item_meta,
    const float* __restrict__ user_emb, const float* __restrict__ rel_emb,
    const float* __restrict__ item_emb, const float* __restrict__ item_emb_r,
    const float* __restrict__ item_bias, const float* __restrict__ rel_bias,
    const float* __restrict__ meta_emb, int B)
{
    const int lane = threadIdx.x & 31;
    const int wid = threadIdx.x >> 5;
    const int b = blockIdx.x * WARPS_PER_BLOCK + wid;

    float seqL = 0.f, relL = 0.f, itmL = 0.f;

    if (b < B) {
        const int uid  = u_id[b];
        const int aid  = anchor_i_id[b];
        const int pid  = pos_i_id[b];
        const int nid  = neg_i_id[b];
        const int nrid = neg_ri_id[b];
        const int prid = pos_r_id[b];
        const int nrel = neg_r_id[b];

        // each lane owns dims [2*lane, 2*lane+1] of D=64
        float2 u   = __ldg((const float2*)user_emb   + (size_t)uid  * 32 + lane);
        float2 ar  = __ldg((const float2*)item_emb_r + (size_t)aid  * 32 + lane);
        float2 a   = __ldg((const float2*)item_emb   + (size_t)aid  * 32 + lane);
        float2 p   = __ldg((const float2*)item_emb   + (size_t)pid  * 32 + lane);
        float2 n   = __ldg((const float2*)item_emb   + (size_t)nid  * 32 + lane);
        float2 nri = __ldg((const float2*)item_emb   + (size_t)nrid * 32 + lane);

        float2 re[3];
#pragma unroll
        for (int r = 0; r < 3; r++)
            re[r] = __ldg((const float2*)rel_emb + r * 32 + lane);

        float2 am[4], pm[4], nm[4];
#pragma unroll
        for (int g = 0; g < 4; g++) {
            int ma = __ldg(item_meta + (size_t)aid * 4 + g);
            int mp = __ldg(item_meta + (size_t)pid * 4 + g);
            int mn = __ldg(item_meta + (size_t)nid * 4 + g);
            am[g] = __ldg((const float2*)meta_emb + (size_t)ma * 32 + lane);
            pm[g] = __ldg((const float2*)meta_emb + (size_t)mp * 32 + lane);
            nm[g] = __ldg((const float2*)meta_emb + (size_t)mn * 32 + lane);
        }

        // ---- relation prediction: softmax_r( rel_bias[r] - ||u + a_r - rel_emb[r]||^2 )
        float rw[3];
#pragma unroll
        for (int r = 0; r < 3; r++) {
            float dx = u.x + ar.x - re[r].x;
            float dy = u.y + ar.y - re[r].y;
            rw[r] = __ldg(rel_bias + r) - wsum(dx * dx + dy * dy);
        }
        float mx = fmaxf(rw[0], fmaxf(rw[1], rw[2]));
        float ssum = 0.f;
#pragma unroll
        for (int r = 0; r < 3; r++) { rw[r] = expf(rw[r] - mx); ssum += rw[r]; }
        float inv = 1.f / ssum;
#pragma unroll
        for (int r = 0; r < 3; r++) rw[r] *= inv;

        // ---- attention coef: softmax_c( i_plus[c] . w2 )  (wu & biases cancel in softmax)
        float2 w2 = ((const float2*)g_w2)[lane];
        float cf[5];
        cf[0] = wsum(a.x * w2.x + a.y * w2.y);
#pragma unroll
        for (int g = 0; g < 4; g++)
            cf[1 + g] = wsum(am[g].x * w2.x + am[g].y * w2.y);
        mx = cf[0];
#pragma unroll
        for (int c = 1; c < 5; c++) mx = fmaxf(mx, cf[c]);
        ssum = 0.f;
#pragma unroll
        for (int c = 0; c < 5; c++) { cf[c] = expf(cf[c] - mx); ssum += cf[c]; }
        inv = 1.f / ssum;
#pragma unroll
        for (int c = 0; c < 5; c++) cf[c] *= inv;

        // ---- rbar = sum_r rel[r]*rue[r],  srp = per-lane partial of sum_r rel[r]*||rue[r]||^2
        const float GAMMA = 0.5f;
        float2 rbar;
        rbar.x = GAMMA * (rw[0] * re[0].x + rw[1] * re[1].x + rw[2] * re[2].x) + (1.f - GAMMA) * u.x;
        rbar.y = GAMMA * (rw[0] * re[0].y + rw[1] * re[1].y + rw[2] * re[2].y) + (1.f - GAMMA) * u.y;
        float srp = GAMMA * (rw[0] * (re[0].x * re[0].x + re[0].y * re[0].y)
                           + rw[1] * (re[1].x * re[1].x + re[1].y * re[1].y)
                           + rw[2] * (re[2].x * re[2].x + re[2].y * re[2].y))
                  + (1.f - GAMMA) * (u.x * u.x + u.y * u.y);

        // ---- predict_score via dist factorization:
        //   score = -( sum_c cf||d_c||^2 + 2*(sum_c cf*d_c).rbar + sum_r rel||rue||^2 )
        float sp, sn;
        {
            float sd = 0.f, dbx = 0.f, dby = 0.f;
            float dx = a.x - p.x, dy = a.y - p.y;
            sd += cf[0] * (dx * dx + dy * dy); dbx += cf[0] * dx; dby += cf[0] * dy;
#pragma unroll
            for (int g = 0; g < 4; g++) {
                dx = am[g].x - pm[g].x; dy = am[g].y - pm[g].y;
                sd += cf[1 + g] * (dx * dx + dy * dy);
                dbx += cf[1 + g] * dx; dby += cf[1 + g] * dy;
            }
            sp = sd + 2.f * (dbx * rbar.x + dby * rbar.y) + srp;
        }
        {
            float sd = 0.f, dbx = 0.f, dby = 0.f;
            float dx = a.x - n.x, dy = a.y - n.y;
            sd += cf[0] * (dx * dx + dy * dy); dbx += cf[0] * dx; dby += cf[0] * dy;
#pragma unroll
            for (int g = 0; g < 4; g++) {
                dx = am[g].x - nm[g].x; dy = am[g].y - nm[g].y;
                sd += cf[1 + g] * (dx * dx + dy * dy);
                dbx += cf[1 + g] * dx; dby += cf[1 + g] * dy;
            }
            sn = sd + 2.f * (dbx * rbar.x + dby * rbar.y) + srp;
        }
        float biasP = __ldg(item_bias + pid);
        float biasN = __ldg(item_bias + nid);
        float posR = biasP - wsum(sp);
        float negR = biasN - wsum(sn);
        seqL = nlsig(posR - negR);

        // ---- relation loss
        float prs = (prid == 0) ? rw[0] : ((prid == 1) ? rw[1] : rw[2]);
        float nrs = (nrel == 0) ? rw[0] : ((nrel == 1) ? rw[1] : rw[2]);
        relL = nlsig(prs - nrs);

        // ---- item loss
        float2 iir;
        iir.x = (prid == 0) ? re[0].x : ((prid == 1) ? re[1].x : re[2].x);
        iir.y = (prid == 0) ? re[0].y : ((prid == 1) ? re[1].y : re[2].y);
        float tx = a.x + iir.x - p.x, ty = a.y + iir.y - p.y;
        float posI = biasP - wsum(tx * tx + ty * ty);
        tx = a.x + iir.x - nri.x; ty = a.y + iir.y - nri.y;
        float negI = __ldg(item_bias + nrid) - wsum(tx * tx + ty * ty);
        itmL = nlsig(posI - negI);
    }

    // ---- deterministic block-level partial sum
    __shared__ float sh[WARPS_PER_BLOCK][3];
    if (lane == 0) { sh[wid][0] = seqL; sh[wid][1] = relL; sh[wid][2] = itmL; }
    __syncthreads();
    if (threadIdx.x == 0) {
        float s0 = 0.f, s1 = 0.f, s2 = 0.f;
#pragma unroll
        for (int w = 0; w < WARPS_PER_BLOCK; w++) {
            s0 += sh[w][0]; s1 += sh[w][1]; s2 += sh[w][2];
        }
        g_partials[blockIdx.x * 3 + 0] = s0;
        g_partials[blockIdx.x * 3 + 1] = s1;
        g_partials[blockIdx.x * 3 + 2] = s2;
    }
}

__global__ void actr_reduce(float* __restrict__ out, int nblocks, float invB) {
    __shared__ float sh[3];
    int lane = threadIdx.x & 31;
    int wid = threadIdx.x >> 5;
    if (wid < 3) {
        float s = 0.f;
        for (int i = lane; i < nblocks; i += 32) s += g_partials[i * 3 + wid];
        s = wsum(s) * invB;
        if (lane == 0) sh[wid] = s;
    }
    __syncthreads();
    if (threadIdx.x == 0) {
        float seq = sh[0], rel = sh[1], itm = sh[2];
        out[0] = seq + rel + itm;   // loss (ALPHA=BETA=1)
        out[1] = rel;               // relation_loss
        out[2] = seq;               // seq_loss
        out[3] = itm;               // item_loss
    }
}

extern "C" void kernel_launch(void* const* d_in, const int* in_sizes, int n_in,
                              void* d_out, int out_size) {
    const int*   u_id       = (const int*)d_in[0];
    const int*   anchor_i   = (const int*)d_in[1];
    const int*   pos_r      = (const int*)d_in[2];
    const int*   pos_i      = (const int*)d_in[3];
    const int*   neg_r      = (const int*)d_in[4];
    const int*   neg_i      = (const int*)d_in[5];
    const int*   neg_ri     = (const int*)d_in[6];
    const int*   item_meta  = (const int*)d_in[7];
    const float* user_emb   = (const float*)d_in[8];
    const float* rel_emb    = (const float*)d_in[9];
    const float* item_emb   = (const float*)d_in[10];
    const float* item_emb_r = (const float*)d_in[11];
    const float* item_bias  = (const float*)d_in[12];
    const float* rel_bias   = (const float*)d_in[13];
    const float* meta_emb   = (const float*)d_in[14];
    const float* att_w_W    = (const float*)d_in[15];
    const float* att_v_W    = (const float*)d_in[17];

    const int B = in_sizes[0];
    int nblocks = (B + WARPS_PER_BLOCK - 1) / WARPS_PER_BLOCK;
    if (nblocks > MAX_BLOCKS) nblocks = MAX_BLOCKS;  // B=16384 -> 2048

    precompute_w2<<<1, 64>>>(att_w_W, att_v_W);
    actr_main<<<nblocks, THREADS>>>(u_id, anchor_i, pos_r, pos_i, neg_r, neg_i, neg_ri,
                                    item_meta, user_emb, rel_emb, item_emb, item_emb_r,
                                    item_bias, rel_bias, meta_emb, B);
    actr_reduce<<<1, 96>>>((float*)d_out, nblocks, 1.0f / (float)B);
}